// round 9
// baseline (speedup 1.0000x reference)
#include <cuda_runtime.h>
#include <cuda_bf16.h>
#include <cstdint>

// Conv2d 3x3 s1 p1 NCHW, implicit GEMM, mma.sync tf32, halo-tile B assembly.
// 512 threads / 16 warps, warp tile 64ko x 32px. CTA: 128ko x 256px (16x16).
// K as 8 chunks of (8 ch x 9 taps). Octet t: tap fixed, channel = tig+4h.

#define HW    112
#define IMG   (HW * HW)
#define KTOT  576
#define KOUT  128

#define PW        100                     // sA pitch (words), 100%32==4
#define A_BYTES   (KOUT * PW * 4)         // 51200
#define H_PITCH   20                      // halo pitch (floats)
#define H_CH      (18 * H_PITCH)          // 360 words/channel, 360%32==8
#define H_BYTES   (8 * H_CH * 4)          // 11520
#define STAGE_B   (A_BYTES + H_BYTES)     // 62720
#define NBUF      3
#define SMEM_TOTAL (NBUF * STAGE_B)       // 188160

__device__ __forceinline__ uint32_t cvt_tf32(float x) {
    uint32_t r;
    asm("cvt.rna.tf32.f32 %0, %1;" : "=r"(r) : "f"(x));
    return r;
}
__device__ __forceinline__ uint32_t smem_u32(const void* p) {
    uint32_t a;
    asm("{ .reg .u64 t; cvta.to.shared.u64 t, %1; cvt.u32.u64 %0, t; }" : "=r"(a) : "l"(p));
    return a;
}
__device__ __forceinline__ float lds_f32(uint32_t a) {
    float v;
    asm volatile("ld.shared.f32 %0, [%1];" : "=f"(v) : "r"(a));
    return v;
}
__device__ __forceinline__ void cpa16(uint32_t dst, const float* src) {
    asm volatile("cp.async.cg.shared.global [%0], [%1], 16;" :: "r"(dst), "l"(src));
}
__device__ __forceinline__ void cpa4(uint32_t dst, const float* src, int sz) {
    asm volatile("cp.async.ca.shared.global [%0], [%1], 4, %2;"
                 :: "r"(dst), "l"(src), "r"(sz));
}
__device__ __forceinline__ void cpa_commit() {
    asm volatile("cp.async.commit_group;" ::: "memory");
}
__device__ __forceinline__ void mma8(float* d, const uint32_t* a, const uint32_t* b) {
    asm volatile(
        "mma.sync.aligned.m16n8k8.row.col.f32.tf32.tf32.f32 "
        "{%0,%1,%2,%3}, {%4,%5,%6,%7}, {%8,%9}, {%0,%1,%2,%3};"
        : "+f"(d[0]), "+f"(d[1]), "+f"(d[2]), "+f"(d[3])
        : "r"(a[0]), "r"(a[1]), "r"(a[2]), "r"(a[3]), "r"(b[0]), "r"(b[1]));
}

__global__ __launch_bounds__(512, 1)
void conv_mma_halo2(const float* __restrict__ x,
                    const float* __restrict__ w,
                    const float* __restrict__ bias,
                    float* __restrict__ out)
{
    extern __shared__ __align__(16) char dsm[];
    const uint32_t sb = smem_u32(dsm);

    const int tid  = threadIdx.x;
    const int warp = tid >> 5;
    const int lane = tid & 31;
    const int g    = lane >> 2;
    const int tig  = lane & 3;
    const int warp_m = warp >> 3;        // 0..1  (64 ko)
    const int warp_n = warp & 7;         // 0..7  (32 px = 2 rows x 16 cols)

    const int tile = blockIdx.x;         // 0..48
    const int n    = blockIdx.y;         // 0..31
    const int py0  = (tile / 7) * 16;
    const int px0  = (tile % 7) * 16;

    const float* xn = x + (size_t)n * 64 * IMG;

    // ---- staging tables (divisions at init only) ----
    // A: 2304 16B-quads over 512 threads -> 5 slots (last partial)
    int      asrc[5];
    uint32_t adst[5];
    unsigned avalid = 0;
#pragma unroll
    for (int j = 0; j < 5; j++) {
        const int q = tid + j * 512;
        if (q < 2304) avalid |= 1u << j;
        const int qq = (q < 2304) ? q : 0;
        const int ko = qq / 18;
        const int qk = qq - ko * 18;
        asrc[j] = ko * KTOT + qk * 4;
        adst[j] = (uint32_t)(ko * (PW * 4) + qk * 16);
    }
    // Halo: 8 channels x 324 cells; 64 threads per channel, 6 slots
    const int hc = tid >> 6;
    const int hs = tid & 63;
    int      hsrc[6];
    uint32_t hdst[6];
    unsigned hinr = 0, hok = 0;
#pragma unroll
    for (int j = 0; j < 6; j++) {
        const int  cell = hs + j * 64;
        const bool inr  = cell < 324;
        const int  cl   = inr ? cell : 0;
        const int  r    = cl / 18;
        const int  col  = cl - r * 18;
        const int  gy   = py0 - 1 + r;
        const int  gx   = px0 - 1 + col;
        const bool ok   = inr && ((unsigned)gy < (unsigned)HW) &&
                          ((unsigned)gx < (unsigned)HW);
        if (inr) hinr |= 1u << j;
        if (ok)  hok  |= 1u << j;
        hsrc[j] = ok ? (gy * HW + gx) : 0;
        hdst[j] = (uint32_t)(hc * (H_CH * 4) + r * (H_PITCH * 4) + col * 4);
    }

    float acc[4][4][4];
#pragma unroll
    for (int mi = 0; mi < 4; mi++)
#pragma unroll
        for (int ni = 0; ni < 4; ni++)
#pragma unroll
            for (int r = 0; r < 4; r++) acc[mi][ni][r] = 0.0f;

    auto stage = [&](int cc, int buf) {
        const uint32_t ab = sb + (uint32_t)buf * STAGE_B;
        const uint32_t hb = ab + A_BYTES;
        const float* wsrc = w + cc * 72;
#pragma unroll
        for (int j = 0; j < 5; j++)
            if (avalid & (1u << j)) cpa16(ab + adst[j], wsrc + asrc[j]);
        const float* xc = xn + (size_t)(cc * 8 + hc) * IMG;
#pragma unroll
        for (int j = 0; j < 6; j++)
            if (hinr & (1u << j))
                cpa4(hb + hdst[j], xc + hsrc[j], ((hok >> j) & 1u) ? 4 : 0);
        cpa_commit();
    };

    // fragment base addresses (bytes)
    const uint32_t aoff0 = (uint32_t)(((warp_m * 64 + g) * PW + tig * 9) * 4);
    const uint32_t boff0 = (uint32_t)((tig * H_CH + warp_n * 2 * H_PITCH + g) * 4);

    auto compute = [&](int buf) {
        const uint32_t ab = sb + (uint32_t)buf * STAGE_B;
        const uint32_t a0 = ab + aoff0;
        const uint32_t b0 = ab + A_BYTES + boff0;
#pragma unroll
        for (int t = 0; t < 9; t++) {
            const int dyt = t / 3, dxt = t - dyt * 3;     // compile-time
            uint32_t af[4][4], bf[4][2];
#pragma unroll
            for (int mi = 0; mi < 4; mi++) {
                const uint32_t am = a0 + (uint32_t)(mi * 16 * PW * 4 + t * 4);
                af[mi][0] = cvt_tf32(lds_f32(am));
                af[mi][1] = cvt_tf32(lds_f32(am + 8 * PW * 4));
                af[mi][2] = cvt_tf32(lds_f32(am + 36 * 4));
                af[mi][3] = cvt_tf32(lds_f32(am + 8 * PW * 4 + 36 * 4));
            }
#pragma unroll
            for (int ni = 0; ni < 4; ni++) {
                const uint32_t bm = b0 +
                    (uint32_t)((((ni >> 1) + dyt) * H_PITCH + (ni & 1) * 8 + dxt) * 4);
                bf[ni][0] = cvt_tf32(lds_f32(bm));
                bf[ni][1] = cvt_tf32(lds_f32(bm + 4 * H_CH * 4));
            }
#pragma unroll
            for (int mi = 0; mi < 4; mi++)
#pragma unroll
                for (int ni = 0; ni < 4; ni++)
                    mma8(acc[mi][ni], af[mi], bf[ni]);
        }
    };

    // ---- pipeline: 3 buffers, 2 stages in flight ----
    stage(0, 0);
    stage(1, 1);
#pragma unroll 1
    for (int cc = 0; cc < 8; cc++) {
        if (cc < 7) asm volatile("cp.async.wait_group 1;" ::: "memory");
        else        asm volatile("cp.async.wait_group 0;" ::: "memory");
        __syncthreads();
        if (cc + 2 < 8) stage(cc + 2, (cc + 2) % 3);
        compute(cc % 3);
    }

    // ---- epilogue: bias + float2 stores ----
#pragma unroll
    for (int mi = 0; mi < 4; mi++) {
        const int ko0 = warp_m * 64 + mi * 16 + g;
        const float bv0 = __ldg(bias + ko0);
        const float bv1 = __ldg(bias + ko0 + 8);
        float* o0 = out + ((size_t)n * KOUT + ko0) * IMG;
        float* o1 = o0 + 8 * IMG;
#pragma unroll
        for (int ni = 0; ni < 4; ni++) {
            const int p  = warp_n * 32 + ni * 8 + 2 * tig;
            const int oy = py0 + (p >> 4);
            const int ox = px0 + (p & 15);
            const size_t off = (size_t)oy * HW + ox;
            *(float2*)(o0 + off) = make_float2(acc[mi][ni][0] + bv0, acc[mi][ni][1] + bv0);
            *(float2*)(o1 + off) = make_float2(acc[mi][ni][2] + bv1, acc[mi][ni][3] + bv1);
        }
    }
}

extern "C" void kernel_launch(void* const* d_in, const int* in_sizes, int n_in,
                              void* d_out, int out_size)
{
    const float* x = (const float*)d_in[0];
    const float* w = (const float*)d_in[1];
    const float* b = (const float*)d_in[2];
    float* out = (float*)d_out;

    cudaFuncSetAttribute(conv_mma_halo2,
                         cudaFuncAttributeMaxDynamicSharedMemorySize, SMEM_TOTAL);

    dim3 grid(49, 32);
    dim3 block(512);
    conv_mma_halo2<<<grid, block, SMEM_TOTAL>>>(x, w, b, out);
}

// round 10
// speedup vs baseline: 1.9031x; 1.9031x over previous
#include <cuda_runtime.h>
#include <cuda_bf16.h>
#include <cstdint>

// Conv2d 3x3 s1 p1 NCHW, implicit GEMM, mma.sync tf32.
// A (weights): pre-converted to tf32 in fragment order (g_wtf, L2-resident),
//              loaded per-tap via coalesced LDG.128 — no smem, no staging.
// B (x):       halo tile 8ch x 18x18 in smem via 16B cp.async, frags via LDS.
// CTA: 128ko x 256px (16x16 tile, one image), 256 thr, 8 warps, warp 64x64.

#define HW    112
#define IMG   (HW * HW)
#define KTOT  576
#define KOUT  128

#define H_ROW   24                       // halo row pitch (words)
#define H_CH    440                      // per-channel words (18*24+8); 440%32==24
#define H_BYTES (8 * H_CH * 4)           // 14080
#define NBUF    4
#define SMEM_TOTAL (NBUF * H_BYTES)      // 56320

__device__ uint32_t g_wtf[8 * 9 * 2 * 4 * 128];   // 73728 words = 288 KB

__device__ __forceinline__ uint32_t cvt_tf32(float x) {
    uint32_t r;
    asm("cvt.rna.tf32.f32 %0, %1;" : "=r"(r) : "f"(x));
    return r;
}
__device__ __forceinline__ uint32_t smem_u32(const void* p) {
    uint32_t a;
    asm("{ .reg .u64 t; cvta.to.shared.u64 t, %1; cvt.u32.u64 %0, t; }" : "=r"(a) : "l"(p));
    return a;
}
__device__ __forceinline__ float lds_f32(uint32_t a) {
    float v;
    asm volatile("ld.shared.f32 %0, [%1];" : "=f"(v) : "r"(a));
    return v;
}
__device__ __forceinline__ void cpa16z(uint32_t dst, const float* src, int sz) {
    asm volatile("cp.async.cg.shared.global [%0], [%1], 16, %2;"
                 :: "r"(dst), "l"(src), "r"(sz));
}
__device__ __forceinline__ void cpa4(uint32_t dst, const float* src, int sz) {
    asm volatile("cp.async.ca.shared.global [%0], [%1], 4, %2;"
                 :: "r"(dst), "l"(src), "r"(sz));
}
__device__ __forceinline__ void mma8(float* d, const uint4& a, const uint32_t* b) {
    asm volatile(
        "mma.sync.aligned.m16n8k8.row.col.f32.tf32.tf32.f32 "
        "{%0,%1,%2,%3}, {%4,%5,%6,%7}, {%8,%9}, {%0,%1,%2,%3};"
        : "+f"(d[0]), "+f"(d[1]), "+f"(d[2]), "+f"(d[3])
        : "r"(a.x), "r"(a.y), "r"(a.z), "r"(a.w), "r"(b[0]), "r"(b[1]));
}

// ---- prep: w[ko][k] f32 -> g_wtf fragment-ordered tf32 ----
__global__ void prep_w(const float* __restrict__ w) {
    const int i  = blockIdx.x * 256 + threadIdx.x;   // 0..73727
    const int ko = i / KTOT;
    const int k  = i - ko * KTOT;
    const int wm = ko >> 6, mi = (ko >> 4) & 3, h = (ko >> 3) & 1, g = ko & 7;
    const int cc = k / 72;
    const int kr = k - cc * 72;
    const int ch = kr / 9;
    const int t  = kr - ch * 9;
    const int tig = ch & 3, c1 = ch >> 2;
    const int dst = ((((cc * 9 + t) * 2 + wm) * 4 + mi) << 7) + (g * 4 + tig) * 4 +
                    (h + 2 * c1);
    g_wtf[dst] = cvt_tf32(w[i]);
}

__global__ __launch_bounds__(256, 1)
void conv_mma_wreg(const float* __restrict__ x,
                   const float* __restrict__ bias,
                   float* __restrict__ out)
{
    extern __shared__ __align__(16) char dsm[];
    const uint32_t sb = smem_u32(dsm);

    const int tid  = threadIdx.x;
    const int warp = tid >> 5;
    const int lane = tid & 31;
    const int g    = lane >> 2;
    const int tig  = lane & 3;
    const int warp_m = warp >> 2;        // 0..1
    const int warp_n = warp & 3;         // 0..3

    const int tile = blockIdx.x;         // 0..48
    const int n    = blockIdx.y;         // 0..31
    const int py0  = (tile / 7) * 16;
    const int px0  = (tile % 7) * 16;

    const float* xn = x + (size_t)n * 64 * IMG;

    // ---- B staging precompute: thread<144 owns one (ch,row) halo row ----
    const bool  hact = tid < 144;
    const int   hch  = hact ? tid / 18 : 0;
    const int   hrow = hact ? tid - hch * 18 : 0;
    const int   gy   = py0 - 1 + hrow;
    const bool  gyok = hact && ((unsigned)gy < (unsigned)HW);
    const int   srco = hch * IMG + (gyok ? gy : 0) * HW;   // + cc*8*IMG per chunk
    const uint32_t hdb = (uint32_t)((hch * H_CH + hrow * H_ROW + 3) * 4);
    const int   szq  = gyok ? 16 : 0;
    const int   szl  = (gyok && px0 > 0) ? 4 : 0;
    const int   szt  = (gyok && px0 + 16 < HW) ? 4 : 0;

    auto stage = [&](int cc, int buf) {
        if (hact) {
            const uint32_t db = sb + (uint32_t)buf * H_BYTES + hdb;
            const float* sr = xn + cc * 8 * IMG + srco;
            cpa4(db, sr + px0 - 1, szl);
#pragma unroll
            for (int q = 0; q < 4; q++)
                cpa16z(db + (uint32_t)((1 + 4 * q) * 4), sr + px0 + 4 * q, szq);
            cpa4(db + 17 * 4, sr + px0 + 16, szt);
        }
        asm volatile("cp.async.commit_group;" ::: "memory");
    };

    // ---- A fragment prefetch from g_wtf ----
    auto ldA = [&](int cc, int t, uint4 a[4]) {
        const uint4* p = (const uint4*)g_wtf +
                         (size_t)(((cc * 9 + t) * 2 + warp_m) * 4) * 32 + lane;
        a[0] = __ldg(p);
        a[1] = __ldg(p + 32);
        a[2] = __ldg(p + 64);
        a[3] = __ldg(p + 96);
    };

    float acc[4][8][4];
#pragma unroll
    for (int mi = 0; mi < 4; mi++)
#pragma unroll
        for (int ni = 0; ni < 8; ni++)
#pragma unroll
            for (int r = 0; r < 4; r++) acc[mi][ni][r] = 0.0f;

    uint4 afc[4], afn[4];
    ldA(0, 0, afc);

    // B fragment base (bytes): word 3 + tig*H_CH + warp_n*4*H_ROW + g
    const uint32_t boff0 = (uint32_t)((3 + tig * H_CH + warp_n * 4 * H_ROW + g) * 4);

    // ---- pipeline ----
    stage(0, 0);
    stage(1, 1);
    stage(2, 2);
#pragma unroll 1
    for (int cc = 0; cc < 8; cc++) {
        if (cc < 6)       asm volatile("cp.async.wait_group 2;" ::: "memory");
        else if (cc == 6) asm volatile("cp.async.wait_group 1;" ::: "memory");
        else              asm volatile("cp.async.wait_group 0;" ::: "memory");
        __syncthreads();
        if (cc + 3 < 8) stage(cc + 3, (cc + 3) & 3);

        const uint32_t b0 = sb + (uint32_t)(cc & 3) * H_BYTES + boff0;
#pragma unroll
        for (int t = 0; t < 9; t++) {
            const int dyt = t / 3, dxt = t - dyt * 3;          // compile-time
            const bool last = (cc == 7) && (t == 8);
            if (t < 8)      ldA(cc, t + 1, afn);
            else if (!last) ldA(cc + 1, 0, afn);

            uint32_t bf[8][2];
#pragma unroll
            for (int ni = 0; ni < 8; ni++) {
                const uint32_t bm = b0 +
                    (uint32_t)((((ni >> 1) + dyt) * H_ROW + (ni & 1) * 8 + dxt) * 4);
                bf[ni][0] = cvt_tf32(lds_f32(bm));
                bf[ni][1] = cvt_tf32(lds_f32(bm + 4 * H_CH * 4));
            }
#pragma unroll
            for (int mi = 0; mi < 4; mi++)
#pragma unroll
                for (int ni = 0; ni < 8; ni++)
                    mma8(acc[mi][ni], afc[mi], bf[ni]);
            if (!last) {
#pragma unroll
                for (int mi = 0; mi < 4; mi++) afc[mi] = afn[mi];
            }
        }
    }

    // ---- epilogue: bias + float2 stores ----
#pragma unroll
    for (int mi = 0; mi < 4; mi++) {
        const int ko0 = warp_m * 64 + mi * 16 + g;
        const float bv0 = __ldg(bias + ko0);
        const float bv1 = __ldg(bias + ko0 + 8);
        float* o0 = out + ((size_t)n * KOUT + ko0) * IMG;
        float* o1 = o0 + 8 * IMG;
#pragma unroll
        for (int ni = 0; ni < 8; ni++) {
            const int p  = warp_n * 64 + ni * 8 + 2 * tig;
            const int oy = py0 + (p >> 4);
            const int ox = px0 + (p & 15);
            const size_t off = (size_t)oy * HW + ox;
            *(float2*)(o0 + off) = make_float2(acc[mi][ni][0] + bv0, acc[mi][ni][1] + bv0);
            *(float2*)(o1 + off) = make_float2(acc[mi][ni][2] + bv1, acc[mi][ni][3] + bv1);
        }
    }
}

extern "C" void kernel_launch(void* const* d_in, const int* in_sizes, int n_in,
                              void* d_out, int out_size)
{
    const float* x = (const float*)d_in[0];
    const float* w = (const float*)d_in[1];
    const float* b = (const float*)d_in[2];
    float* out = (float*)d_out;

    prep_w<<<288, 256>>>(w);

    cudaFuncSetAttribute(conv_mma_wreg,
                         cudaFuncAttributeMaxDynamicSharedMemorySize, SMEM_TOTAL);
    dim3 grid(49, 32);
    conv_mma_wreg<<<grid, 256, SMEM_TOTAL>>>(x, b, out);
}